// round 3
// baseline (speedup 1.0000x reference)
#include <cuda_runtime.h>
#include <math.h>

#define Bsz   1024
#define Nn    32
#define SP    60
#define SE    10
#define OOUT  5
#define IIN   6
#define GPB   8      // samples per block
#define TPB   128    // 120 active threads: k in [0,60) x g4 in {0,1}, 4 samples each

// ---- shared memory layout (float offsets) ----
#define O_WIH 0
#define O_WHH 10800
#define O_WF  21600
#define O_BIH 26400
#define O_BHH 26580
#define O_BF  26760
#define O_X   26820
#define O_H   27300
#define O_M   27780
#define SMEM_FLOATS 27788

// ---- device scratch (no allocations allowed) ----
__device__ float g_adj[Nn * Nn];
__device__ int   g_fcnt[Nn];
__device__ int   g_flist[Nn][Nn];
__device__ int   g_bcnt[Nn];
__device__ int   g_blist[Nn][Nn];
__device__ float g_rho_f[Nn * Bsz * SP];   // [node][b][60]
__device__ float g_rho_b[Nn * Bsz * SP];
__device__ float g_af[Bsz * SP];
__device__ float g_ab[Bsz * SP];

// ============================================================
// Prep: decode adj (dtype-ambiguous bool) + build ordered edge lists
// ============================================================
__global__ void k_prep(const unsigned char* __restrict__ adj_raw) {
    if (threadIdx.x != 0 || blockIdx.x != 0) return;
    // dtype sniff over first 1024 bytes (safe for int8/float32/int32 buffers)
    int  mode = 2;                  // 0=int8/bool, 1=float32, 2=int32
    bool any_gt1 = false, any_off4 = false;
    for (int t = 0; t < Nn * Nn; t++) {
        unsigned char c = adj_raw[t];
        if (c > 1) { any_gt1 = true; break; }
        if (c == 1 && (t & 3) != 0) any_off4 = true;
    }
    if (any_gt1) mode = 1; else if (any_off4) mode = 0;

    for (int e = 0; e < Nn * Nn; e++) {
        float v;
        if (mode == 1)      v = ((const float*)adj_raw)[e];
        else if (mode == 2) v = (float)(((const int*)adj_raw)[e]);
        else                v = (float)adj_raw[e];
        g_adj[e] = v;
    }
    // fwd: node i consumes edges adj[j][i]!=0, inner scan j ascending
    for (int i = 0; i < Nn; i++) {
        int c = 0;
        for (int j = 0; j < Nn; j++)
            if (g_adj[j * Nn + i] != 0.0f) g_flist[i][c++] = j;
        g_fcnt[i] = c;
    }
    // bwd: node i consumes edges adj[i][j]!=0, inner scan j descending
    for (int i = 0; i < Nn; i++) {
        int c = 0;
        for (int j = Nn - 1; j >= 0; j--)
            if (g_adj[i * Nn + j] != 0.0f) g_blist[i][c++] = j;
        g_bcnt[i] = c;
    }
}

// ============================================================
// GRU step for one thread: output dim k, 4 samples (g4*4+gg)
// ============================================================
__device__ __forceinline__ float sigm(float x) { return 1.0f / (1.0f + expf(-x)); }

__device__ __forceinline__ void gru_step(
    const float* __restrict__ sWih, const float* __restrict__ sWhh,
    const float* __restrict__ sBih, const float* __restrict__ sBhh,
    const float* __restrict__ sX,   const float* __restrict__ sH,
    const float* __restrict__ sM,   int k, int g4, float* hnew)
{
    float air[4] = {0,0,0,0}, aiz[4] = {0,0,0,0}, ain[4] = {0,0,0,0};
    float ahr[4] = {0,0,0,0}, ahz[4] = {0,0,0,0}, ahn[4] = {0,0,0,0};
    const float4* wr = (const float4*)(sWih + k * 60);
    const float4* wz = (const float4*)(sWih + (60 + k) * 60);
    const float4* wn = (const float4*)(sWih + (120 + k) * 60);
    const float4* ur = (const float4*)(sWhh + k * 60);
    const float4* uz = (const float4*)(sWhh + (60 + k) * 60);
    const float4* un = (const float4*)(sWhh + (120 + k) * 60);
    const float4* xb = (const float4*)(sX + g4 * 240);
    const float4* hb = (const float4*)(sH + g4 * 240);

    #pragma unroll 3
    for (int q = 0; q < 15; q++) {
        float4 a = wr[q], b = wz[q], c = wn[q];
        float4 d = ur[q], e = uz[q], f = un[q];
        #pragma unroll
        for (int gg = 0; gg < 4; gg++) {
            float4 xv = xb[gg * 15 + q];
            float4 hv = hb[gg * 15 + q];
            air[gg] += a.x*xv.x + a.y*xv.y + a.z*xv.z + a.w*xv.w;
            aiz[gg] += b.x*xv.x + b.y*xv.y + b.z*xv.z + b.w*xv.w;
            ain[gg] += c.x*xv.x + c.y*xv.y + c.z*xv.z + c.w*xv.w;
            ahr[gg] += d.x*hv.x + d.y*hv.y + d.z*hv.z + d.w*hv.w;
            ahz[gg] += e.x*hv.x + e.y*hv.y + e.z*hv.z + e.w*hv.w;
            ahn[gg] += f.x*hv.x + f.y*hv.y + f.z*hv.z + f.w*hv.w;
        }
    }
    const float b_ri = sBih[k],       b_rh = sBhh[k];
    const float b_zi = sBih[60 + k],  b_zh = sBhh[60 + k];
    const float b_ni = sBih[120 + k], b_nh = sBhh[120 + k];
    #pragma unroll
    for (int gg = 0; gg < 4; gg++) {
        const int g = g4 * 4 + gg;
        float r  = sigm(air[gg] + ahr[gg] + b_ri + b_rh);
        float u  = sigm(aiz[gg] + ahz[gg] + b_zi + b_zh);
        float nv = tanhf(ain[gg] + b_ni + r * (ahn[gg] + b_nh));
        float ho = sH[g * 60 + k];
        float h2 = (1.0f - u) * nv + u * ho;
        hnew[gg] = ho + sM[g] * (h2 - ho);
    }
}

// ============================================================
// Main scan: blocks [0,128) fwd, [128,256) bwd; 8 samples/block
// ============================================================
__global__ void __launch_bounds__(TPB) k_scan(
    const float* __restrict__ has, const float* __restrict__ z, const float* __restrict__ dz,
    const float* __restrict__ Wih_f, const float* __restrict__ Whh_f,
    const float* __restrict__ bih_f, const float* __restrict__ bhh_f,
    const float* __restrict__ Wih_b, const float* __restrict__ Whh_b,
    const float* __restrict__ bih_b, const float* __restrict__ bhh_b,
    const float* __restrict__ Wfp, const float* __restrict__ bfp,
    const float* __restrict__ Wbp, const float* __restrict__ bbp)
{
    extern __shared__ float sm[];
    float* sWih = sm + O_WIH;  float* sWhh = sm + O_WHH;  float* sWf = sm + O_WF;
    float* sBih = sm + O_BIH;  float* sBhh = sm + O_BHH;  float* sBf = sm + O_BF;
    float* sX   = sm + O_X;    float* sH   = sm + O_H;    float* sM  = sm + O_M;

    const int dir = blockIdx.x >> 7;
    const int g0  = (blockIdx.x & 127) * GPB;
    const float* Wih = dir ? Wih_b : Wih_f;
    const float* Whh = dir ? Whh_b : Whh_f;
    const float* bih = dir ? bih_b : bih_f;
    const float* bhh = dir ? bhh_b : bhh_f;
    const float* Wp  = dir ? Wbp   : Wfp;
    const float* bp  = dir ? bbp   : bfp;
    float* grho = dir ? g_rho_b : g_rho_f;

    const int tid = threadIdx.x;
    for (int idx = tid; idx < 10800; idx += TPB) { sWih[idx] = Wih[idx]; sWhh[idx] = Whh[idx]; }
    for (int idx = tid; idx < 4800;  idx += TPB) sWf[idx] = Wp[idx];
    for (int idx = tid; idx < 180;   idx += TPB) { sBih[idx] = bih[idx]; sBhh[idx] = bhh[idx]; }
    for (int idx = tid; idx < 60;    idx += TPB) sBf[idx] = bp[idx];
    __syncthreads();

    const int  k   = tid % 60;
    const int  g4  = tid / 60;
    const bool act = tid < 120;

    // ---- node scan ----
    for (int ii = 0; ii < Nn; ii++) {
        const int i = dir ? (Nn - 1 - ii) : ii;
        if (act) {
            #pragma unroll
            for (int gg = 0; gg < 4; gg++) sH[(g4 * 4 + gg) * 60 + k] = 0.0f;
        }
        __syncthreads();

        const int  cnt = dir ? g_bcnt[i] : g_fcnt[i];
        const int* lst = dir ? g_blist[i] : g_flist[i];
        for (int e = 0; e < cnt; e++) {
            const int j = lst[e];
            if (act) {
                #pragma unroll
                for (int gg = 0; gg < 4; gg++) {
                    const int g = g4 * 4 + gg;
                    sX[g * 60 + k] = grho[((size_t)j * Bsz + g0 + g) * 60 + k];
                }
            }
            if (tid < GPB) sM[tid] = has[(g0 + tid) * Nn + j];
            __syncthreads();
            float hnew[4];
            if (act) gru_step(sWih, sWhh, sBih, sBhh, sX, sH, sM, k, g4, hnew);
            __syncthreads();
            if (act) {
                #pragma unroll
                for (int gg = 0; gg < 4; gg++) sH[(g4 * 4 + gg) * 60 + k] = hnew[gg];
            }
        }
        __syncthreads();

        // projection: rho_i = (tanh)( [h, z_i, dz_i] @ W^T + b )
        if (act) {
            #pragma unroll
            for (int gg = 0; gg < 4; gg++) {
                const int g = g4 * 4 + gg;
                const int b = g0 + g;
                float acc = sBf[k];
                const float4* wf4 = (const float4*)(sWf + k * 80);
                const float4* hh  = (const float4*)(sH + g * 60);
                #pragma unroll
                for (int q = 0; q < 15; q++) {
                    float4 w = wf4[q], x = hh[q];
                    acc += w.x*x.x + w.y*x.y + w.z*x.z + w.w*x.w;
                }
                const float* zp  = z  + ((size_t)b * Nn + i) * SE;
                const float* dzp = dz + ((size_t)b * Nn + i) * SE;
                #pragma unroll
                for (int c = 0; c < SE; c++) acc += sWf[k * 80 + 60 + c] * __ldg(zp + c);
                #pragma unroll
                for (int c = 0; c < SE; c++) acc += sWf[k * 80 + 70 + c] * __ldg(dzp + c);
                if (dir == 0) acc = tanhf(acc);
                grho[((size_t)i * Bsz + b) * 60 + k] = acc;
            }
        }
        __syncthreads();
    }

    // ---- alpha scan ----
    if (act) {
        #pragma unroll
        for (int gg = 0; gg < 4; gg++) sH[(g4 * 4 + gg) * 60 + k] = 0.0f;
    }
    __syncthreads();
    const int steps = dir ? IIN : OOUT;
    for (int s = 0; s < steps; s++) {
        const int i = dir ? (IIN - 1 - s) : (Nn - OOUT + s);
        if (act) {
            #pragma unroll
            for (int gg = 0; gg < 4; gg++) {
                const int g = g4 * 4 + gg;
                sX[g * 60 + k] = grho[((size_t)i * Bsz + g0 + g) * 60 + k];
            }
        }
        if (tid < GPB) sM[tid] = has[(g0 + tid) * Nn + i];
        __syncthreads();
        float hnew[4];
        if (act) gru_step(sWih, sWhh, sBih, sBhh, sX, sH, sM, k, g4, hnew);
        __syncthreads();
        if (act) {
            #pragma unroll
            for (int gg = 0; gg < 4; gg++) sH[(g4 * 4 + gg) * 60 + k] = hnew[gg];
        }
    }
    __syncthreads();
    if (act) {
        float* ga = dir ? g_ab : g_af;
        #pragma unroll
        for (int gg = 0; gg < 4; gg++) {
            const int g = g4 * 4 + gg;
            ga[(g0 + g) * 60 + k] = sH[g * 60 + k];
        }
    }
}

// ============================================================
// role_prob head: thread = (b, n); softmax over 7 roles
// out layout: [0,5120) instr | [5120, 5120+229376) roles | value
// ============================================================
__global__ void k_roles(const float* __restrict__ has,
                        const float* __restrict__ Wu, const float* __restrict__ bu,
                        float* __restrict__ out)
{
    __shared__ float sWu[7 * 120];
    __shared__ float sbu[7];
    const int tid = threadIdx.x;
    for (int idx = tid; idx < 840; idx += blockDim.x) sWu[idx] = Wu[idx];
    if (tid < 7) sbu[tid] = bu[tid];
    __syncthreads();

    const int t = blockIdx.x * blockDim.x + tid;
    const int b = t >> 5;
    const int n = t & 31;

    float acc[7];
    #pragma unroll
    for (int r = 0; r < 7; r++) acc[r] = sbu[r];

    const float4* rf = (const float4*)(g_rho_f + ((size_t)n * Bsz + b) * 60);
    const float4* rb = (const float4*)(g_rho_b + ((size_t)n * Bsz + b) * 60);
    #pragma unroll
    for (int q = 0; q < 15; q++) {
        float4 f = rf[q];
        #pragma unroll
        for (int r = 0; r < 7; r++) {
            float4 w = *(const float4*)(sWu + r * 120 + q * 4);
            acc[r] += w.x*f.x + w.y*f.y + w.z*f.z + w.w*f.w;
        }
    }
    #pragma unroll
    for (int q = 0; q < 15; q++) {
        float4 f = rb[q];
        #pragma unroll
        for (int r = 0; r < 7; r++) {
            float4 w = *(const float4*)(sWu + r * 120 + 60 + q * 4);
            acc[r] += w.x*f.x + w.y*f.y + w.z*f.z + w.w*f.w;
        }
    }
    const float m = has[b * Nn + n];
    float l[7], mx = -1e30f;
    #pragma unroll
    for (int r = 0; r < 7; r++) { l[r] = (m != 0.0f) ? acc[r] : -60.0f; mx = fmaxf(mx, l[r]); }
    float s = 0.0f;
    #pragma unroll
    for (int r = 0; r < 7; r++) { l[r] = expf(l[r] - mx); s += l[r]; }
    const float inv = 1.0f / s;
    float* ro = out + 5120;
    #pragma unroll
    for (int r = 0; r < 7; r++) ro[((size_t)b * 7 + r) * 32 + n] = l[r] * inv;
}

// ============================================================
// instr_prob + value head: thread = b
// ============================================================
__global__ void k_instr(const float* __restrict__ Wa, const float* __restrict__ ba,
                        const float* __restrict__ Wc, const float* __restrict__ bc,
                        float* __restrict__ out)
{
    __shared__ float sWa[5 * 120];
    __shared__ float sba[5];
    __shared__ float sWc[120];
    __shared__ float sbc;
    const int tid = threadIdx.x;
    for (int idx = tid; idx < 600; idx += blockDim.x) sWa[idx] = Wa[idx];
    for (int idx = tid; idx < 120; idx += blockDim.x) sWc[idx] = Wc[idx];
    if (tid < 5) sba[tid] = ba[tid];
    if (tid == 0) sbc = bc[0];
    __syncthreads();

    const int b = blockIdx.x * blockDim.x + tid;

    float acc[5];
    #pragma unroll
    for (int a = 0; a < 5; a++) acc[a] = sba[a];
    float accv = sbc;

    const float4* af = (const float4*)(g_af + (size_t)b * 60);
    const float4* ab = (const float4*)(g_ab + (size_t)b * 60);
    #pragma unroll
    for (int q = 0; q < 15; q++) {
        float4 f = af[q];
        #pragma unroll
        for (int a = 0; a < 5; a++) {
            float4 w = *(const float4*)(sWa + a * 120 + q * 4);
            acc[a] += w.x*f.x + w.y*f.y + w.z*f.z + w.w*f.w;
        }
        float4 wc = *(const float4*)(sWc + q * 4);
        accv += wc.x*f.x + wc.y*f.y + wc.z*f.z + wc.w*f.w;
    }
    #pragma unroll
    for (int q = 0; q < 15; q++) {
        float4 f = ab[q];
        #pragma unroll
        for (int a = 0; a < 5; a++) {
            float4 w = *(const float4*)(sWa + a * 120 + 60 + q * 4);
            acc[a] += w.x*f.x + w.y*f.y + w.z*f.z + w.w*f.w;
        }
        float4 wc = *(const float4*)(sWc + 60 + q * 4);
        accv += wc.x*f.x + wc.y*f.y + wc.z*f.z + wc.w*f.w;
    }
    float mx = -1e30f;
    #pragma unroll
    for (int a = 0; a < 5; a++) mx = fmaxf(mx, acc[a]);
    float s = 0.0f;
    #pragma unroll
    for (int a = 0; a < 5; a++) { acc[a] = expf(acc[a] - mx); s += acc[a]; }
    const float inv = 1.0f / s;
    #pragma unroll
    for (int a = 0; a < 5; a++) out[b * 5 + a] = acc[a] * inv;
    out[5120 + Bsz * 7 * Nn + b] = accv;   // value at offset 234496
}

// ============================================================
extern "C" void kernel_launch(void* const* d_in, const int* in_sizes, int n_in,
                              void* d_out, int out_size)
{
    const float* has   = (const float*)d_in[0];
    const float* z     = (const float*)d_in[1];
    const float* dz    = (const float*)d_in[2];
    const unsigned char* adj = (const unsigned char*)d_in[3];
    const float* Wih_f = (const float*)d_in[4];
    const float* Whh_f = (const float*)d_in[5];
    const float* bih_f = (const float*)d_in[6];
    const float* bhh_f = (const float*)d_in[7];
    const float* Wih_b = (const float*)d_in[8];
    const float* Whh_b = (const float*)d_in[9];
    const float* bih_b = (const float*)d_in[10];
    const float* bhh_b = (const float*)d_in[11];
    const float* Wf    = (const float*)d_in[12];
    const float* bf    = (const float*)d_in[13];
    const float* Wb    = (const float*)d_in[14];
    const float* bb    = (const float*)d_in[15];
    const float* Wa    = (const float*)d_in[16];
    const float* ba    = (const float*)d_in[17];
    const float* Wc    = (const float*)d_in[18];
    const float* bc    = (const float*)d_in[19];
    const float* Wu    = (const float*)d_in[20];
    const float* bu    = (const float*)d_in[21];
    float* out = (float*)d_out;

    const size_t smem = SMEM_FLOATS * sizeof(float);   // ~111 KB
    cudaFuncSetAttribute(k_scan, cudaFuncAttributeMaxDynamicSharedMemorySize, (int)smem);

    k_prep<<<1, 32>>>(adj);
    k_scan<<<256, TPB, smem>>>(has, z, dz,
                               Wih_f, Whh_f, bih_f, bhh_f,
                               Wih_b, Whh_b, bih_b, bhh_b,
                               Wf, bf, Wb, bb);
    k_roles<<<(Bsz * Nn) / 256, 256>>>(has, Wu, bu, out);
    k_instr<<<Bsz / 256, 256>>>(Wa, ba, Wc, bc, out);
}

// round 4
// speedup vs baseline: 1.7514x; 1.7514x over previous
#include <cuda_runtime.h>
#include <math.h>

#define Bsz   1024
#define Nn    32
#define SP    60
#define SE    10
#define OOUT  5
#define IIN   6
#define GPB   8      // samples per block
#define TPB   192    // 180 active: gate g in {0,1,2} x dim k in [0,60); 8 samples each

// ---- shared memory layout (float offsets) ----
#define S_WIH 0        // 10800 (staging for Whh, then permanent Wih)
#define S_WF  10800    // 60*84 padded = 5040
#define S_BF  15840    // 60
#define S_H   15900    // 8*64
#define S_Z   16412    // 8*64
#define S_GHN 16924    // 8*64
#define S_GIN 17436    // 8*64
#define S_RHO 17948    // 8*64
#define S_M   18460    // 8
#define SMEM_FLOATS 18468

// ---- device scratch ----
__device__ int   g_fcnt[Nn];
__device__ int   g_flist[Nn][Nn];
__device__ int   g_bcnt[Nn];
__device__ int   g_blist[Nn][Nn];
__device__ float g_rho_f[Nn * Bsz * SP];        // [node][b][60]
__device__ float g_rho_b[Nn * Bsz * SP];
__device__ float g_af[Bsz * SP];
__device__ float g_ab[Bsz * SP];
__device__ float g_gi_f[Nn * Bsz * 180];        // gi cache: [node][b][gate*60+k], includes bih
__device__ float g_gi_b[Nn * Bsz * 180];

// ============================================================
// Prep: decode adj (dtype-ambiguous bool) + build ordered edge lists
// ============================================================
__global__ void k_prep(const unsigned char* __restrict__ adj_raw) {
    __shared__ float sadj[Nn * Nn];
    __shared__ int s_gt1, s_off4;
    const int tid = threadIdx.x;
    if (tid == 0) { s_gt1 = 0; s_off4 = 0; }
    __syncthreads();
    int f_gt1 = 0, f_off4 = 0;
    for (int t = tid; t < Nn * Nn; t += blockDim.x) {
        unsigned char c = adj_raw[t];
        if (c > 1) f_gt1 = 1;
        if (c == 1 && (t & 3) != 0) f_off4 = 1;
    }
    if (f_gt1)  atomicOr(&s_gt1, 1);
    if (f_off4) atomicOr(&s_off4, 1);
    __syncthreads();
    const int mode = s_gt1 ? 1 : (s_off4 ? 0 : 2);   // 1=float32, 0=int8, 2=int32
    for (int e = tid; e < Nn * Nn; e += blockDim.x) {
        float v;
        if (mode == 1)      v = ((const float*)adj_raw)[e];
        else if (mode == 2) v = (float)(((const int*)adj_raw)[e]);
        else                v = (float)adj_raw[e];
        sadj[e] = v;
    }
    __syncthreads();
    if (tid < Nn) {                       // fwd: edges adj[j][i]!=0, j ascending
        const int i = tid; int c = 0;
        for (int j = 0; j < Nn; j++)
            if (sadj[j * Nn + i] != 0.0f) g_flist[i][c++] = j;
        g_fcnt[i] = c;
    } else if (tid < 2 * Nn) {            // bwd: edges adj[i][j]!=0, j descending
        const int i = tid - Nn; int c = 0;
        for (int j = Nn - 1; j >= 0; j--)
            if (sadj[i * Nn + j] != 0.0f) g_blist[i][c++] = j;
        g_bcnt[i] = c;
    }
}

// ============================================================
// math helpers (via __expf; max err ~1e-6, far under 1e-3 budget)
// ============================================================
__device__ __forceinline__ float sigmf_(float x) {
    return __fdividef(1.0f, 1.0f + __expf(-x));
}
__device__ __forceinline__ float tanhsafe_(float x) {
    float a = fabsf(x);
    float e = __expf(-2.0f * a);
    float t = __fdividef(1.0f - e, 1.0f + e);
    return copysignf(t, x);
}

// ============================================================
// Main scan: blocks [0,128) fwd, [128,256) bwd; 8 samples/block
// thread = (gate g, dim k); Whh row in registers; gi cached per node
// ============================================================
__global__ void __launch_bounds__(TPB, 2) k_scan(
    const float* __restrict__ has, const float* __restrict__ z, const float* __restrict__ dz,
    const float* __restrict__ Wih_f, const float* __restrict__ Whh_f,
    const float* __restrict__ bih_f, const float* __restrict__ bhh_f,
    const float* __restrict__ Wih_b, const float* __restrict__ Whh_b,
    const float* __restrict__ bih_b, const float* __restrict__ bhh_b,
    const float* __restrict__ Wfp, const float* __restrict__ bfp,
    const float* __restrict__ Wbp, const float* __restrict__ bbp)
{
    extern __shared__ float sm[];
    const int dir = blockIdx.x >> 7;
    const int b0  = (blockIdx.x & 127) * GPB;
    const float* Wih = dir ? Wih_b : Wih_f;
    const float* Whh = dir ? Whh_b : Whh_f;
    const float* bih = dir ? bih_b : bih_f;
    const float* bhh = dir ? bhh_b : bhh_f;
    const float* Wp  = dir ? Wbp   : Wfp;
    const float* bp  = dir ? bbp   : bfp;
    float* grho = dir ? g_rho_b : g_rho_f;
    float* gic  = dir ? g_gi_b  : g_gi_f;

    const int  tid = threadIdx.x;
    const int  g   = tid / 60;          // 0=r, 1=z, 2=n (3 -> inactive)
    const int  k   = tid - g * 60;
    const bool act = tid < 180;

    // ---- stage Wf (rows padded to 84 for conflict-free LDS.128) + proj bias
    for (int idx = tid; idx < 4800; idx += TPB)
        sm[S_WF + (idx / 80) * 84 + (idx % 80)] = Wp[idx];
    for (int idx = tid; idx < 60; idx += TPB) sm[S_BF + idx] = bp[idx];

    // ---- stage Whh through smem -> registers (row tid)
    for (int idx = tid; idx < 10800; idx += TPB) sm[S_WIH + idx] = Whh[idx];
    __syncthreads();
    float whh[60];
    if (act) {
        #pragma unroll
        for (int q = 0; q < 15; q++) {
            float4 v = *(const float4*)(sm + S_WIH + tid * 60 + 4 * q);
            whh[4*q] = v.x; whh[4*q+1] = v.y; whh[4*q+2] = v.z; whh[4*q+3] = v.w;
        }
    }
    __syncthreads();
    // ---- now Wih stays resident in smem
    for (int idx = tid; idx < 10800; idx += TPB) sm[S_WIH + idx] = Wih[idx];
    const float my_bih = act ? bih[tid] : 0.0f;
    const float my_bhh = act ? bhh[tid] : 0.0f;
    __syncthreads();

    const float4* sH4   = (const float4*)(sm + S_H);
    const float4* sRHO4 = (const float4*)(sm + S_RHO);
    const float4* sWIH4 = (const float4*)(sm + S_WIH);

    float h_old[GPB];
    float tval[GPB];
    float gi[GPB];

    // ================== node scan ==================
    for (int ii = 0; ii < Nn; ii++) {
        const int i = dir ? (Nn - 1 - ii) : ii;
        if (g == 0) {
            #pragma unroll
            for (int b = 0; b < GPB; b++) { h_old[b] = 0.0f; sm[S_H + b * 64 + k] = 0.0f; }
        }
        __syncthreads();

        const int  cnt = dir ? g_bcnt[i] : g_fcnt[i];
        const int* lst = dir ? g_blist[i] : g_flist[i];

        for (int e = 0; e < cnt; e++) {
            const int j = lst[e];
            if (act) {
                #pragma unroll
                for (int b = 0; b < GPB; b++)
                    gi[b] = gic[((size_t)j * Bsz + b0 + b) * 180 + tid];
            }
            __syncthreads();   // barA: previous pointwise sH writes visible
            if (act) {
                float acc[GPB];
                #pragma unroll
                for (int b = 0; b < GPB; b++) acc[b] = 0.0f;
                #pragma unroll
                for (int q = 0; q < 15; q++) {
                    #pragma unroll
                    for (int b = 0; b < GPB; b++) {
                        float4 hv = sH4[b * 16 + q];
                        acc[b] += whh[4*q]*hv.x + whh[4*q+1]*hv.y
                                + whh[4*q+2]*hv.z + whh[4*q+3]*hv.w;
                    }
                }
                #pragma unroll
                for (int b = 0; b < GPB; b++) tval[b] = gi[b] + acc[b] + my_bhh;
                if (g == 1) {
                    #pragma unroll
                    for (int b = 0; b < GPB; b++) sm[S_Z + b * 64 + k] = tval[b];
                } else if (g == 2) {
                    #pragma unroll
                    for (int b = 0; b < GPB; b++) {
                        sm[S_GHN + b * 64 + k] = acc[b] + my_bhh;
                        sm[S_GIN + b * 64 + k] = gi[b];
                    }
                }
            }
            if (tid < GPB) sm[S_M + tid] = has[(size_t)(b0 + tid) * Nn + j];
            __syncthreads();   // barB
            if (g == 0) {
                #pragma unroll
                for (int b = 0; b < GPB; b++) {
                    float r  = sigmf_(tval[b]);
                    float u  = sigmf_(sm[S_Z + b * 64 + k]);
                    float nv = tanhsafe_(sm[S_GIN + b * 64 + k] + r * sm[S_GHN + b * 64 + k]);
                    float h2 = (1.0f - u) * nv + u * h_old[b];
                    float hn = h_old[b] + sm[S_M + b] * (h2 - h_old[b]);
                    h_old[b] = hn;
                    sm[S_H + b * 64 + k] = hn;
                }
            }
        }
        __syncthreads();   // barC: final sH visible

        // ---- projection: rho[b][kk] = (tanh)( [h,z_i,dz_i] . Wf[kk] + bf[kk] )
        #pragma unroll
        for (int m = 0; m < 3; m++) {
            const int o = tid + 180 * m;
            if (act && o < 480) {
                const int bb = o / 60, kk = o - bb * 60;
                float acc = sm[S_BF + kk];
                const float4* wf4 = (const float4*)(sm + S_WF + kk * 84);
                #pragma unroll
                for (int q = 0; q < 15; q++) {
                    float4 w = wf4[q], x = sH4[bb * 16 + q];
                    acc += w.x*x.x + w.y*x.y + w.z*x.z + w.w*x.w;
                }
                const float* zp  = z  + ((size_t)(b0 + bb) * Nn + i) * SE;
                const float* dzp = dz + ((size_t)(b0 + bb) * Nn + i) * SE;
                #pragma unroll
                for (int c = 0; c < SE; c++) acc += sm[S_WF + kk * 84 + 60 + c] * __ldg(zp + c);
                #pragma unroll
                for (int c = 0; c < SE; c++) acc += sm[S_WF + kk * 84 + 70 + c] * __ldg(dzp + c);
                if (dir == 0) acc = tanhsafe_(acc);
                sm[S_RHO + bb * 64 + kk] = acc;
                grho[((size_t)i * Bsz + b0 + bb) * 60 + kk] = acc;
            }
        }
        __syncthreads();   // barD: sRho visible

        // ---- gi for this node: gi[tid][b] = bih[tid] + rho[b] . Wih[tid]
        if (act) {
            float gacc[GPB];
            #pragma unroll
            for (int b = 0; b < GPB; b++) gacc[b] = my_bih;
            #pragma unroll
            for (int q = 0; q < 15; q++) {
                float4 w = sWIH4[tid * 15 + q];
                #pragma unroll
                for (int b = 0; b < GPB; b++) {
                    float4 rv = sRHO4[b * 16 + q];
                    gacc[b] += w.x*rv.x + w.y*rv.y + w.z*rv.z + w.w*rv.w;
                }
            }
            #pragma unroll
            for (int b = 0; b < GPB; b++)
                gic[((size_t)i * Bsz + b0 + b) * 180 + tid] = gacc[b];
        }
        // next-iteration __syncthreads (via zeroing barrier) orders gi reads/writes
    }

    // ================== alpha scan ==================
    if (g == 0) {
        #pragma unroll
        for (int b = 0; b < GPB; b++) { h_old[b] = 0.0f; sm[S_H + b * 64 + k] = 0.0f; }
    }
    __syncthreads();
    const int steps = dir ? IIN : OOUT;
    for (int s = 0; s < steps; s++) {
        const int i = dir ? (IIN - 1 - s) : (Nn - OOUT + s);
        if (act) {
            #pragma unroll
            for (int b = 0; b < GPB; b++)
                gi[b] = gic[((size_t)i * Bsz + b0 + b) * 180 + tid];
        }
        __syncthreads();
        if (act) {
            float acc[GPB];
            #pragma unroll
            for (int b = 0; b < GPB; b++) acc[b] = 0.0f;
            #pragma unroll
            for (int q = 0; q < 15; q++) {
                #pragma unroll
                for (int b = 0; b < GPB; b++) {
                    float4 hv = sH4[b * 16 + q];
                    acc[b] += whh[4*q]*hv.x + whh[4*q+1]*hv.y
                            + whh[4*q+2]*hv.z + whh[4*q+3]*hv.w;
                }
            }
            #pragma unroll
            for (int b = 0; b < GPB; b++) tval[b] = gi[b] + acc[b] + my_bhh;
            if (g == 1) {
                #pragma unroll
                for (int b = 0; b < GPB; b++) sm[S_Z + b * 64 + k] = tval[b];
            } else if (g == 2) {
                #pragma unroll
                for (int b = 0; b < GPB; b++) {
                    sm[S_GHN + b * 64 + k] = acc[b] + my_bhh;
                    sm[S_GIN + b * 64 + k] = gi[b];
                }
            }
        }
        if (tid < GPB) sm[S_M + tid] = has[(size_t)(b0 + tid) * Nn + i];
        __syncthreads();
        if (g == 0) {
            #pragma unroll
            for (int b = 0; b < GPB; b++) {
                float r  = sigmf_(tval[b]);
                float u  = sigmf_(sm[S_Z + b * 64 + k]);
                float nv = tanhsafe_(sm[S_GIN + b * 64 + k] + r * sm[S_GHN + b * 64 + k]);
                float h2 = (1.0f - u) * nv + u * h_old[b];
                float hn = h_old[b] + sm[S_M + b] * (h2 - h_old[b]);
                h_old[b] = hn;
                sm[S_H + b * 64 + k] = hn;
            }
        }
    }
    if (g == 0) {
        float* ga = dir ? g_ab : g_af;
        #pragma unroll
        for (int b = 0; b < GPB; b++)
            ga[(size_t)(b0 + b) * 60 + k] = h_old[b];
    }
}

// ============================================================
// role_prob head: thread = (b, n); softmax over 7 roles
// out layout: [0,5120) instr | [5120,234496) roles | [234496,235520) value
// ============================================================
__global__ void k_roles(const float* __restrict__ has,
                        const float* __restrict__ Wu, const float* __restrict__ bu,
                        float* __restrict__ out)
{
    __shared__ float sWu[7 * 120];
    __shared__ float sbu[7];
    const int tid = threadIdx.x;
    for (int idx = tid; idx < 840; idx += blockDim.x) sWu[idx] = Wu[idx];
    if (tid < 7) sbu[tid] = bu[tid];
    __syncthreads();

    const int t = blockIdx.x * blockDim.x + tid;
    const int b = t >> 5;
    const int n = t & 31;

    float acc[7];
    #pragma unroll
    for (int r = 0; r < 7; r++) acc[r] = sbu[r];

    const float4* rf = (const float4*)(g_rho_f + ((size_t)n * Bsz + b) * 60);
    const float4* rb = (const float4*)(g_rho_b + ((size_t)n * Bsz + b) * 60);
    #pragma unroll
    for (int q = 0; q < 15; q++) {
        float4 f = rf[q];
        #pragma unroll
        for (int r = 0; r < 7; r++) {
            float4 w = *(const float4*)(sWu + r * 120 + q * 4);
            acc[r] += w.x*f.x + w.y*f.y + w.z*f.z + w.w*f.w;
        }
    }
    #pragma unroll
    for (int q = 0; q < 15; q++) {
        float4 f = rb[q];
        #pragma unroll
        for (int r = 0; r < 7; r++) {
            float4 w = *(const float4*)(sWu + r * 120 + 60 + q * 4);
            acc[r] += w.x*f.x + w.y*f.y + w.z*f.z + w.w*f.w;
        }
    }
    const float m = has[b * Nn + n];
    float l[7], mx = -1e30f;
    #pragma unroll
    for (int r = 0; r < 7; r++) { l[r] = (m != 0.0f) ? acc[r] : -60.0f; mx = fmaxf(mx, l[r]); }
    float s = 0.0f;
    #pragma unroll
    for (int r = 0; r < 7; r++) { l[r] = expf(l[r] - mx); s += l[r]; }
    const float inv = 1.0f / s;
    float* ro = out + 5120;
    #pragma unroll
    for (int r = 0; r < 7; r++) ro[((size_t)b * 7 + r) * 32 + n] = l[r] * inv;
}

// ============================================================
// instr_prob + value head: 4 lanes per sample, shfl-reduced
// ============================================================
__global__ void k_instr(const float* __restrict__ Wa, const float* __restrict__ ba,
                        const float* __restrict__ Wc, const float* __restrict__ bc,
                        float* __restrict__ out)
{
    __shared__ float sWa[5 * 120];
    __shared__ float sWc[120];
    __shared__ float sba[5];
    __shared__ float sbc;
    const int tid = threadIdx.x;
    for (int idx = tid; idx < 600; idx += blockDim.x) sWa[idx] = Wa[idx];
    for (int idx = tid; idx < 120; idx += blockDim.x) sWc[idx] = Wc[idx];
    if (tid < 5) sba[tid] = ba[tid];
    if (tid == 0) sbc = bc[0];
    __syncthreads();

    const int t    = blockIdx.x * blockDim.x + tid;
    const int b    = t >> 2;
    const int lane = t & 3;

    float acc[6];
    #pragma unroll
    for (int a = 0; a < 6; a++) acc[a] = 0.0f;

    const float4* af = (const float4*)(g_af + (size_t)b * 60);
    const float4* ab = (const float4*)(g_ab + (size_t)b * 60);
    for (int q = lane; q < 30; q += 4) {
        float4 f = (q < 15) ? af[q] : ab[q - 15];
        #pragma unroll
        for (int a = 0; a < 5; a++) {
            float4 w = *(const float4*)(sWa + a * 120 + q * 4);
            acc[a] += w.x*f.x + w.y*f.y + w.z*f.z + w.w*f.w;
        }
        float4 wc = *(const float4*)(sWc + q * 4);
        acc[5] += wc.x*f.x + wc.y*f.y + wc.z*f.z + wc.w*f.w;
    }
    #pragma unroll
    for (int off = 1; off < 4; off <<= 1) {
        #pragma unroll
        for (int a = 0; a < 6; a++)
            acc[a] += __shfl_xor_sync(0xffffffffu, acc[a], off);
    }
    if (lane == 0) {
        float l[5], mx = -1e30f;
        #pragma unroll
        for (int a = 0; a < 5; a++) { l[a] = acc[a] + sba[a]; mx = fmaxf(mx, l[a]); }
        float s = 0.0f;
        #pragma unroll
        for (int a = 0; a < 5; a++) { l[a] = expf(l[a] - mx); s += l[a]; }
        const float inv = 1.0f / s;
        #pragma unroll
        for (int a = 0; a < 5; a++) out[b * 5 + a] = l[a] * inv;
        out[5120 + Bsz * 7 * Nn + b] = acc[5] + sbc;   // value @ 234496
    }
}

// ============================================================
extern "C" void kernel_launch(void* const* d_in, const int* in_sizes, int n_in,
                              void* d_out, int out_size)
{
    const float* has   = (const float*)d_in[0];
    const float* z     = (const float*)d_in[1];
    const float* dz    = (const float*)d_in[2];
    const unsigned char* adj = (const unsigned char*)d_in[3];
    const float* Wih_f = (const float*)d_in[4];
    const float* Whh_f = (const float*)d_in[5];
    const float* bih_f = (const float*)d_in[6];
    const float* bhh_f = (const float*)d_in[7];
    const float* Wih_b = (const float*)d_in[8];
    const float* Whh_b = (const float*)d_in[9];
    const float* bih_b = (const float*)d_in[10];
    const float* bhh_b = (const float*)d_in[11];
    const float* Wf    = (const float*)d_in[12];
    const float* bf    = (const float*)d_in[13];
    const float* Wb    = (const float*)d_in[14];
    const float* bb    = (const float*)d_in[15];
    const float* Wa    = (const float*)d_in[16];
    const float* ba    = (const float*)d_in[17];
    const float* Wc    = (const float*)d_in[18];
    const float* bc    = (const float*)d_in[19];
    const float* Wu    = (const float*)d_in[20];
    const float* bu    = (const float*)d_in[21];
    float* out = (float*)d_out;

    const size_t smem = SMEM_FLOATS * sizeof(float);   // ~72 KB
    cudaFuncSetAttribute(k_scan, cudaFuncAttributeMaxDynamicSharedMemorySize, (int)smem);

    k_prep<<<1, 256>>>(adj);
    k_scan<<<256, TPB, smem>>>(has, z, dz,
                               Wih_f, Whh_f, bih_f, bhh_f,
                               Wih_b, Whh_b, bih_b, bhh_b,
                               Wf, bf, Wb, bb);
    k_roles<<<(Bsz * Nn) / 256, 256>>>(has, Wu, bu, out);
    k_instr<<<(Bsz * 4) / 256, 256>>>(Wa, ba, Wc, bc, out);
}